// round 13
// baseline (speedup 1.0000x reference)
#include <cuda_runtime.h>
#include <cuda_bf16.h>
#include <cstdint>

#define NN 1024
#define BB 8
#define DIN 64
#define DOUT 64
#define EMB 16
#define DPE 16
#define KIO 8192   // 2*64*64

// ---- device scratch (no allocations allowed) ----
// e stored CANONICALLY only (upper-tri tiles); lower-tri reads use ldmatrix.trans.
__device__ __nv_bfloat16 g_e_hi[(size_t)BB * NN * NN];   // 16 MB
__device__ __nv_bfloat16 g_e_lo[(size_t)BB * NN * NN];   // 16 MB
__device__ __nv_bfloat16 g_sim_hi[NN * NN];              // 2 MB
__device__ __nv_bfloat16 g_sim_lo[NN * NN];              // 2 MB
__device__ __nv_bfloat16 g_xs_hi[BB * NN * DIN];         // 1 MB  (x*Sinv)
__device__ __nv_bfloat16 g_xs_lo[BB * NN * DIN];         // 1 MB
__device__ __nv_bfloat16 g_sxT_hi[NN * BB * DIN];        // 1 MB
__device__ __nv_bfloat16 g_sxT_lo[NN * BB * DIN];        // 1 MB
__device__ float g_w[NN * KIO];           // 32 MB  weights[n][k][i][o]
__device__ float g_bias[NN * DOUT];       // 256 KB
__device__ float g_part[BB * NN * 16];    // 512 KB row-sum partials
__device__ float g_sxT[NN * BB * DIN];    // 2 MB
__device__ float g_s1[NN * BB * DIN];     // 2 MB

// ---------- helpers ----------
static __device__ __forceinline__ unsigned int s2u(const void* p) {
    return (unsigned int)__cvta_generic_to_shared(p);
}
static __device__ __forceinline__ void ldsm_x4(unsigned r[4], unsigned int addr) {
    asm volatile("ldmatrix.sync.aligned.m8n8.x4.shared.b16 {%0,%1,%2,%3}, [%4];"
        : "=r"(r[0]), "=r"(r[1]), "=r"(r[2]), "=r"(r[3]) : "r"(addr));
}
static __device__ __forceinline__ void ldsm_x4_t(unsigned r[4], unsigned int addr) {
    asm volatile("ldmatrix.sync.aligned.m8n8.x4.trans.shared.b16 {%0,%1,%2,%3}, [%4];"
        : "=r"(r[0]), "=r"(r[1]), "=r"(r[2]), "=r"(r[3]) : "r"(addr));
}
static __device__ __forceinline__ void mma16816(float c[4], const unsigned a[4], const unsigned b0, const unsigned b1) {
    asm volatile("mma.sync.aligned.m16n8k16.row.col.f32.bf16.bf16.f32 "
        "{%0,%1,%2,%3}, {%4,%5,%6,%7}, {%8,%9}, {%0,%1,%2,%3};"
        : "+f"(c[0]), "+f"(c[1]), "+f"(c[2]), "+f"(c[3])
        : "r"(a[0]), "r"(a[1]), "r"(a[2]), "r"(a[3]), "r"(b0), "r"(b1));
}
static __device__ __forceinline__ void cpa16(void* dst, const void* src) {
    unsigned int d = s2u(dst);
    asm volatile("cp.async.ca.shared.global [%0], [%1], 16;" :: "r"(d), "l"(src));
}
#define CP_COMMIT() asm volatile("cp.async.commit_group;" ::: "memory")
#define CP_WAIT1()  asm volatile("cp.async.wait_group 1;" ::: "memory")
#define CP_WAIT0()  asm volatile("cp.async.wait_group 0;" ::: "memory")

static __device__ __forceinline__ void split_store(float v, __nv_bfloat16* hi, __nv_bfloat16* lo, size_t off) {
    __nv_bfloat16 h = __float2bfloat16(v);
    hi[off] = h;
    lo[off] = __float2bfloat16(v - __bfloat162float(h));
}
static __device__ __forceinline__ void split_pair(float v0, float v1,
                                                  __nv_bfloat162& hv, __nv_bfloat162& lv) {
    hv = __floats2bfloat162_rn(v0, v1);
    float2 hf = __bfloat1622float2(hv);
    lv = __floats2bfloat162_rn(v0 - hf.x, v1 - hf.y);
}

// e^{-d} for d >= 0, FFMA-only (no MUFU). Max rel err ~2e-8.
static __device__ __forceinline__ float fexp_neg(float d) {
    float z = d * -1.442695040888963f;       // log2(e)
    z = fmaxf(z, -126.0f);
    float n = rintf(z);
    float f = z - n;
    float p = 1.54035304e-4f;
    p = fmaf(p, f, 1.33335581e-3f);
    p = fmaf(p, f, 9.61812911e-3f);
    p = fmaf(p, f, 5.55041087e-2f);
    p = fmaf(p, f, 2.40226507e-1f);
    p = fmaf(p, f, 6.93147181e-1f);
    p = fmaf(p, f, 1.0f);
    int e = (int)n;
    return p * __int_as_float((127 + e) << 23);
}

// ---------------------------------------------------------------------------
// K0: sim = softmax(relu(E E^T), axis=1) -> bf16 hi/lo.  one block per row
// ---------------------------------------------------------------------------
__global__ __launch_bounds__(256) void sim_kernel(const float* __restrict__ E) {
    const int i = blockIdx.x;
    const int t = threadIdx.x;
    __shared__ float Ei[EMB];
    __shared__ float red[256];
    if (t < EMB) Ei[t] = E[i * EMB + t];
    __syncthreads();

    float v[4];
    float mx = -1e30f;
#pragma unroll
    for (int r = 0; r < 4; r++) {
        int j = t + r * 256;
        const float4* Ej = reinterpret_cast<const float4*>(E + j * EMB);
        float acc = 0.f;
#pragma unroll
        for (int q = 0; q < 4; q++) {
            float4 e4 = Ej[q];
            acc += Ei[q * 4 + 0] * e4.x + Ei[q * 4 + 1] * e4.y
                 + Ei[q * 4 + 2] * e4.z + Ei[q * 4 + 3] * e4.w;
        }
        acc = fmaxf(acc, 0.f);
        v[r] = acc;
        mx = fmaxf(mx, acc);
    }
    red[t] = mx; __syncthreads();
    for (int s = 128; s > 0; s >>= 1) { if (t < s) red[t] = fmaxf(red[t], red[t + s]); __syncthreads(); }
    mx = red[0]; __syncthreads();

    float sum = 0.f;
#pragma unroll
    for (int r = 0; r < 4; r++) { v[r] = fexp_neg(mx - v[r]); sum += v[r]; }
    red[t] = sum; __syncthreads();
    for (int s = 128; s > 0; s >>= 1) { if (t < s) red[t] += red[t + s]; __syncthreads(); }
    float inv = 1.0f / red[0];
#pragma unroll
    for (int r = 0; r < 4; r++)
        split_store(v[r] * inv, g_sim_hi, g_sim_lo, (size_t)i * NN + t + r * 256);
}

// ---------------------------------------------------------------------------
// K1: weights[n, kio] = sum_d E[n,d] * Wp[d, kio]  via bf16 mma (3-pass split).
// ---------------------------------------------------------------------------
__global__ __launch_bounds__(256) void weights_mma_kernel(const float* __restrict__ E,
                                                          const float* __restrict__ Wp) {
    const int kio0 = blockIdx.x * 256;
    const int n0 = blockIdx.y * 64;
    const int t = threadIdx.x;
    const int warp = t >> 5, lane = t & 31;
    const int g = lane >> 2, tg = lane & 3;
    const int lrow = lane & 15;
    const int lcol = (lane & 16) >> 1;

    __shared__ __nv_bfloat16 Ah[64][24], Al[64][24];     // E tile [n][d]
    __shared__ __nv_bfloat16 Bh[16][264], Bl[16][264];   // Wp tile [d][kio]

    {
        int r = t >> 2, q4 = (t & 3) * 4;
        float4 v = *reinterpret_cast<const float4*>(&E[(n0 + r) * EMB + q4]);
        __nv_bfloat162 h0, l0, h1, l1;
        split_pair(v.x, v.y, h0, l0);
        split_pair(v.z, v.w, h1, l1);
        *reinterpret_cast<__nv_bfloat162*>(&Ah[r][q4]) = h0;
        *reinterpret_cast<__nv_bfloat162*>(&Ah[r][q4 + 2]) = h1;
        *reinterpret_cast<__nv_bfloat162*>(&Al[r][q4]) = l0;
        *reinterpret_cast<__nv_bfloat162*>(&Al[r][q4 + 2]) = l1;
    }
#pragma unroll
    for (int l = 0; l < 4; l++) {
        int idx = t + l * 256;
        int r = idx >> 6, c4 = (idx & 63) * 4;
        float4 v = *reinterpret_cast<const float4*>(&Wp[(size_t)r * KIO + kio0 + c4]);
        __nv_bfloat162 h0, l0, h1, l1;
        split_pair(v.x, v.y, h0, l0);
        split_pair(v.z, v.w, h1, l1);
        *reinterpret_cast<__nv_bfloat162*>(&Bh[r][c4]) = h0;
        *reinterpret_cast<__nv_bfloat162*>(&Bh[r][c4 + 2]) = h1;
        *reinterpret_cast<__nv_bfloat162*>(&Bl[r][c4]) = l0;
        *reinterpret_cast<__nv_bfloat162*>(&Bl[r][c4 + 2]) = l1;
    }
    __syncthreads();

    unsigned Bfh[4][2], Bfl[4][2];
#pragma unroll
    for (int nb = 0; nb < 2; nb++) {
        unsigned tmp[4];
        ldsm_x4_t(tmp, s2u(&Bh[lrow][warp * 32 + nb * 16 + lcol]));
        Bfh[nb * 2][0] = tmp[0]; Bfh[nb * 2][1] = tmp[1];
        Bfh[nb * 2 + 1][0] = tmp[2]; Bfh[nb * 2 + 1][1] = tmp[3];
        ldsm_x4_t(tmp, s2u(&Bl[lrow][warp * 32 + nb * 16 + lcol]));
        Bfl[nb * 2][0] = tmp[0]; Bfl[nb * 2][1] = tmp[1];
        Bfl[nb * 2 + 1][0] = tmp[2]; Bfl[nb * 2 + 1][1] = tmp[3];
    }

    float acc[4][4][4] = {};
#pragma unroll
    for (int mf = 0; mf < 4; mf++) {
        unsigned A_h[4], A_l[4];
        ldsm_x4(A_h, s2u(&Ah[mf * 16 + lrow][lcol]));
        ldsm_x4(A_l, s2u(&Al[mf * 16 + lrow][lcol]));
#pragma unroll
        for (int f = 0; f < 4; f++) {
            mma16816(acc[mf][f], A_h, Bfh[f][0], Bfh[f][1]);
            mma16816(acc[mf][f], A_h, Bfl[f][0], Bfl[f][1]);
            mma16816(acc[mf][f], A_l, Bfh[f][0], Bfh[f][1]);
        }
    }

#pragma unroll
    for (int mf = 0; mf < 4; mf++)
#pragma unroll
        for (int f = 0; f < 4; f++)
#pragma unroll
            for (int h = 0; h < 2; h++) {
                int row = n0 + mf * 16 + g + h * 8;
                int col = kio0 + warp * 32 + f * 8 + tg * 2;
                *reinterpret_cast<float2*>(&g_w[(size_t)row * KIO + col]) =
                    make_float2(acc[mf][f][h * 2], acc[mf][f][h * 2 + 1]);
            }
}

// K1b: bias[n,o] = sum_d E[n,d] * bp[d,o]
__global__ __launch_bounds__(256) void bias_kernel(const float* __restrict__ E,
                                                   const float* __restrict__ bp) {
    int idx = blockIdx.x * 256 + threadIdx.x;       // 65536
    int n = idx >> 6, o = idx & 63;
    float acc = 0.f;
#pragma unroll
    for (int d = 0; d < EMB; d++) acc += E[n * EMB + d] * bp[d * DOUT + o];
    g_bias[idx] = acc;
}

// ---------------------------------------------------------------------------
// K2: e[b,i,j] = exp(-L1(pa_i, pa_j)) -> bf16 hi/lo, canonical tiles only.
// Reg-capped to 64 (minBlocks=4) — kernel is issue/occupancy bound.
// ---------------------------------------------------------------------------
__global__ __launch_bounds__(256, 4) void e_kernel(const float* __restrict__ pa) {
    const int b = blockIdx.y;
    int rem = blockIdx.x, ti = 0;
    while (rem >= 16 - ti) { rem -= 16 - ti; ti++; }
    const int tjt = ti + rem;
    const int i0 = ti * 64, j0 = tjt * 64;
    const int t = threadIdx.x;
    const int cp = t & 31, rg = t >> 5;
    const int c0 = cp * 2;

    __shared__ float paI[64][20];
    __shared__ float paJ[64][20];
    __shared__ float vS[64][65];
    __shared__ float cpS[8][64];
    __shared__ float rpS[4][64];

    const float* paB = pa + (size_t)b * NN * DPE;
    {
        int r = t >> 2, q4 = (t & 3) * 4;
        *reinterpret_cast<float4*>(&paI[r][q4]) =
            *reinterpret_cast<const float4*>(&paB[(i0 + r) * DPE + q4]);
        *reinterpret_cast<float4*>(&paJ[r][q4]) =
            *reinterpret_cast<const float4*>(&paB[(j0 + r) * DPE + q4]);
    }
    __syncthreads();

    float pj0[16], pj1[16];
#pragma unroll
    for (int q = 0; q < 4; q++) {
        float4 u = *reinterpret_cast<const float4*>(&paJ[c0][q * 4]);
        pj0[q * 4 + 0] = u.x; pj0[q * 4 + 1] = u.y; pj0[q * 4 + 2] = u.z; pj0[q * 4 + 3] = u.w;
        float4 w = *reinterpret_cast<const float4*>(&paJ[c0 + 1][q * 4]);
        pj1[q * 4 + 0] = w.x; pj1[q * 4 + 1] = w.y; pj1[q * 4 + 2] = w.z; pj1[q * 4 + 3] = w.w;
    }

    const unsigned baseD = (unsigned)((b * NN + i0) * NN + j0);
    float cps0 = 0.f, cps1 = 0.f;
#pragma unroll
    for (int s = 0; s < 8; s++) {
        int i = rg * 8 + s;
        float4 p0 = *reinterpret_cast<const float4*>(&paI[i][0]);
        float4 p1 = *reinterpret_cast<const float4*>(&paI[i][4]);
        float4 p2 = *reinterpret_cast<const float4*>(&paI[i][8]);
        float4 p3 = *reinterpret_cast<const float4*>(&paI[i][12]);
        float d0 = (((fabsf(p0.x - pj0[0])  + fabsf(p0.y - pj0[1]))
                  +  (fabsf(p0.z - pj0[2])  + fabsf(p0.w - pj0[3])))
                 +  ((fabsf(p1.x - pj0[4])  + fabsf(p1.y - pj0[5]))
                  +  (fabsf(p1.z - pj0[6])  + fabsf(p1.w - pj0[7]))))
                 + (((fabsf(p2.x - pj0[8])  + fabsf(p2.y - pj0[9]))
                  +  (fabsf(p2.z - pj0[10]) + fabsf(p2.w - pj0[11])))
                 +  ((fabsf(p3.x - pj0[12]) + fabsf(p3.y - pj0[13]))
                  +  (fabsf(p3.z - pj0[14]) + fabsf(p3.w - pj0[15]))));
        float d1 = (((fabsf(p0.x - pj1[0])  + fabsf(p0.y - pj1[1]))
                  +  (fabsf(p0.z - pj1[2])  + fabsf(p0.w - pj1[3])))
                 +  ((fabsf(p1.x - pj1[4])  + fabsf(p1.y - pj1[5]))
                  +  (fabsf(p1.z - pj1[6])  + fabsf(p1.w - pj1[7]))))
                 + (((fabsf(p2.x - pj1[8])  + fabsf(p2.y - pj1[9]))
                  +  (fabsf(p2.z - pj1[10]) + fabsf(p2.w - pj1[11])))
                 +  ((fabsf(p3.x - pj1[12]) + fabsf(p3.y - pj1[13]))
                  +  (fabsf(p3.z - pj1[14]) + fabsf(p3.w - pj1[15]))));
        float v0 = fexp_neg(d0), v1 = fexp_neg(d1);
        vS[i][c0] = v0; vS[i][c0 + 1] = v1;
        cps0 += v0; cps1 += v1;
        __nv_bfloat162 hv, lv; split_pair(v0, v1, hv, lv);
        unsigned off = baseD + (unsigned)i * NN + c0;
        *reinterpret_cast<__nv_bfloat162*>(g_e_hi + off) = hv;
        *reinterpret_cast<__nv_bfloat162*>(g_e_lo + off) = lv;
    }
    cpS[rg][c0] = cps0; cpS[rg][c0 + 1] = cps1;
    __syncthreads();

    {
        int r = t & 63, qq = t >> 6;
        float s = 0.f;
#pragma unroll
        for (int c = 0; c < 16; c++) s += vS[r][qq * 16 + c];
        rpS[qq][r] = s;
    }
    __syncthreads();

    if (t < 64) {
        float rowP = rpS[0][t] + rpS[1][t] + rpS[2][t] + rpS[3][t];
        g_part[((size_t)b * NN + i0 + t) * 16 + tjt] = rowP;
    } else if (t < 128 && ti != tjt) {
        int c = t - 64;
        float colP = 0.f;
#pragma unroll
        for (int q = 0; q < 8; q++) colP += cpS[q][c];
        g_part[((size_t)b * NN + j0 + c) * 16 + ti] = colP;
    }
}

// ---------------------------------------------------------------------------
// K3: merged Sinv + xs:  xs[row,d] = x[row,d] / sum_k part[row][k]
// ---------------------------------------------------------------------------
__global__ __launch_bounds__(256) void sinv_xs_kernel(const float* __restrict__ x) {
    const int row0 = blockIdx.x * 16;
    const int t = threadIdx.x;
    __shared__ float sInv[16];
    if (t < 16) {
        const float* p = g_part + (size_t)(row0 + t) * 16;
        float s = 0.f;
#pragma unroll
        for (int k = 0; k < 16; k++) s += p[k];
        sInv[t] = 1.0f / s;
    }
    __syncthreads();
    const int rloc = t >> 4, d4 = (t & 15) * 4;
    const size_t row = row0 + rloc;
    float4 v = *reinterpret_cast<const float4*>(&x[row * DIN + d4]);
    float s = sInv[rloc];
    v.x *= s; v.y *= s; v.z *= s; v.w *= s;
    __nv_bfloat162 h0, l0, h1, l1;
    split_pair(v.x, v.y, h0, l0);
    split_pair(v.z, v.w, h1, l1);
    *reinterpret_cast<__nv_bfloat162*>(&g_xs_hi[row * DIN + d4]) = h0;
    *reinterpret_cast<__nv_bfloat162*>(&g_xs_hi[row * DIN + d4 + 2]) = h1;
    *reinterpret_cast<__nv_bfloat162*>(&g_xs_lo[row * DIN + d4]) = l0;
    *reinterpret_cast<__nv_bfloat162*>(&g_xs_lo[row * DIN + d4 + 2]) = l1;
}

// ---------------------------------------------------------------------------
// K4: sxT[m][b][d] = sum_c e[b,m,c] * xs[b,c,d]  via bf16 mma (3-pass split)
// Split-K (2 warpgroups, BK=64), 3-stage cp.async ring, ONE sync per iter.
// Lower-tri K-chunks read transposed via ldmatrix.trans.
// grid (16 m-tiles, 8 b)
// ---------------------------------------------------------------------------
__global__ __launch_bounds__(256) void sx_mma_kernel() {
    const int b = blockIdx.y, mt = blockIdx.x, m0 = mt * 64;
    const int t = threadIdx.x;
    const int warp = t >> 5, lane = t & 31;
    const int wg = warp >> 2, w4 = warp & 3;
    const int g = lane >> 2, tg = lane & 3;

    __shared__ __nv_bfloat16 Ah[3][64][72], Al[3][64][72];
    __shared__ __nv_bfloat16 Bh[3][64][72], Bl[3][64][72];
    __shared__ float redS[4][16][64];

    const __nv_bfloat16* eHiB = g_e_hi + (size_t)b * NN * NN;
    const __nv_bfloat16* eLoB = g_e_lo + (size_t)b * NN * NN;
    const __nv_bfloat16* xHi = g_xs_hi + (size_t)b * NN * DIN;
    const __nv_bfloat16* xLo = g_xs_lo + (size_t)b * NN * DIN;

    float acc[8][4] = {};
    const int lrow = lane & 15;
    const int lcol = (lane & 16) >> 1;
    const int trow = ((lane & 16) >> 1) | (lane & 7);   // trans ldsm row
    const int tcol = lane & 8;                          // trans ldsm col

    auto issue = [&](int st, int chunk) {
        int c0 = chunk * 64;
        bool tr = (chunk < mt);
#pragma unroll
        for (int l = 0; l < 2; l++) {
            int idx = t + l * 256;
            int r = idx >> 3, q = (idx & 7) * 8;
            size_t src = tr ? ((size_t)(c0 + r) * NN + m0 + q)
                            : ((size_t)(m0 + r) * NN + c0 + q);
            cpa16(&Ah[st][r][q], eHiB + src);
            cpa16(&Al[st][r][q], eLoB + src);
        }
#pragma unroll
        for (int l = 0; l < 2; l++) {
            int idx = t + l * 256;
            int r = idx >> 3, q = (idx & 7) * 8;
            cpa16(&Bh[st][r][q], &xHi[(size_t)(c0 + r) * DIN + q]);
            cpa16(&Bl[st][r][q], &xLo[(size_t)(c0 + r) * DIN + q]);
        }
    };

    issue(0, 0); CP_COMMIT();
    issue(1, 1); CP_COMMIT();
    for (int it = 0; it < 16; it++) {
        int cur = it % 3;
        if (it < 15) CP_WAIT1(); else CP_WAIT0();
        __syncthreads();
        const bool tr = (it < mt);

#pragma unroll
        for (int k16 = 0; k16 < 2; k16++) {
            int kk = wg * 2 + k16;
            unsigned A_h[4], A_l[4];
            if (tr) {
                ldsm_x4_t(A_h, s2u(&Ah[cur][kk * 16 + trow][w4 * 16 + tcol]));
                ldsm_x4_t(A_l, s2u(&Al[cur][kk * 16 + trow][w4 * 16 + tcol]));
            } else {
                ldsm_x4(A_h, s2u(&Ah[cur][w4 * 16 + lrow][kk * 16 + lcol]));
                ldsm_x4(A_l, s2u(&Al[cur][w4 * 16 + lrow][kk * 16 + lcol]));
            }
            unsigned Bfh[8][2], Bfl[8][2];
#pragma unroll
            for (int nb = 0; nb < 4; nb++) {
                unsigned tmp[4];
                ldsm_x4_t(tmp, s2u(&Bh[cur][kk * 16 + lrow][nb * 16 + lcol]));
                Bfh[nb * 2][0] = tmp[0]; Bfh[nb * 2][1] = tmp[1];
                Bfh[nb * 2 + 1][0] = tmp[2]; Bfh[nb * 2 + 1][1] = tmp[3];
                ldsm_x4_t(tmp, s2u(&Bl[cur][kk * 16 + lrow][nb * 16 + lcol]));
                Bfl[nb * 2][0] = tmp[0]; Bfl[nb * 2][1] = tmp[1];
                Bfl[nb * 2 + 1][0] = tmp[2]; Bfl[nb * 2 + 1][1] = tmp[3];
            }
#pragma unroll
            for (int f = 0; f < 8; f++) {
                mma16816(acc[f], A_h, Bfh[f][0], Bfh[f][1]);
                mma16816(acc[f], A_h, Bfl[f][0], Bfl[f][1]);
                mma16816(acc[f], A_l, Bfh[f][0], Bfh[f][1]);
            }
        }
        if (it + 2 < 16) { issue((it + 2) % 3, it + 2); CP_COMMIT(); }
    }

    __syncthreads();
    if (wg == 1) {
#pragma unroll
        for (int f = 0; f < 8; f++)
#pragma unroll
            for (int h = 0; h < 2; h++)
                *reinterpret_cast<float2*>(&redS[w4][g + h * 8][f * 8 + tg * 2]) =
                    make_float2(acc[f][h * 2], acc[f][h * 2 + 1]);
    }
    __syncthreads();
    if (wg == 0) {
        const int m_lo = m0 + w4 * 16 + g;
#pragma unroll
        for (int f = 0; f < 8; f++) {
            int col = f * 8 + tg * 2;
#pragma unroll
            for (int h = 0; h < 2; h++) {
                float2 r = *reinterpret_cast<const float2*>(&redS[w4][g + h * 8][col]);
                float vx = acc[f][h * 2] + r.x, vy = acc[f][h * 2 + 1] + r.y;
                int m = m_lo + h * 8;
                size_t o = ((size_t)m * BB + b) * DIN + col;
                *reinterpret_cast<float2*>(&g_sxT[o]) = make_float2(vx, vy);
                __nv_bfloat162 hv, lv; split_pair(vx, vy, hv, lv);
                *reinterpret_cast<__nv_bfloat162*>(&g_sxT_hi[o]) = hv;
                *reinterpret_cast<__nv_bfloat162*>(&g_sxT_lo[o]) = lv;
            }
        }
    }
}

// ---------------------------------------------------------------------------
// K5: s1[n][bd] = sum_m sim[n,m] * sxT[m][bd]  — split-K, 3-stage ring.
// grid (16 n-tiles, 8 bd-tiles)
// ---------------------------------------------------------------------------
__global__ __launch_bounds__(256) void s1_mma_kernel() {
    const int n0 = blockIdx.x * 64, bd0 = blockIdx.y * 64;
    const int t = threadIdx.x;
    const int warp = t >> 5, lane = t & 31;
    const int wg = warp >> 2, w4 = warp & 3;
    const int g = lane >> 2, tg = lane & 3;

    __shared__ __nv_bfloat16 Ah[3][64][72], Al[3][64][72];
    __shared__ __nv_bfloat16 Bh[3][64][72], Bl[3][64][72];
    __shared__ float redS[4][16][64];

    const __nv_bfloat16* aHi = g_sim_hi + (size_t)n0 * NN;
    const __nv_bfloat16* aLo = g_sim_lo + (size_t)n0 * NN;

    float acc[8][4] = {};
    const int lrow = lane & 15;
    const int lcol = (lane & 16) >> 1;

    auto issue = [&](int st, int chunk) {
        int c0 = chunk * 64;
#pragma unroll
        for (int l = 0; l < 2; l++) {
            int idx = t + l * 256;
            int r = idx >> 3, q = (idx & 7) * 8;
            cpa16(&Ah[st][r][q], &aHi[(size_t)r * NN + c0 + q]);
            cpa16(&Al[st][r][q], &aLo[(size_t)r * NN + c0 + q]);
        }
#pragma unroll
        for (int l = 0; l < 2; l++) {
            int idx = t + l * 256;
            int r = idx >> 3, q = (idx & 7) * 8;
            cpa16(&Bh[st][r][q], &g_sxT_hi[(size_t)(c0 + r) * (BB * DIN) + bd0 + q]);
            cpa16(&Bl[st][r][q], &g_sxT_lo[(size_t)(c0 + r) * (BB * DIN) + bd0 + q]);
        }
    };

    issue(0, 0); CP_COMMIT();
    issue(1, 1); CP_COMMIT();
    for (int it = 0; it < 16; it++) {
        int cur = it % 3;
        if (it < 15) CP_WAIT1(); else CP_WAIT0();
        __syncthreads();

#pragma unroll
        for (int k16 = 0; k16 < 2; k16++) {
            int kk = wg * 2 + k16;
            unsigned A_h[4], A_l[4];
            ldsm_x4(A_h, s2u(&Ah[cur][w4 * 16 + lrow][kk * 16 + lcol]));
            ldsm_x4(A_l, s2u(&Al[cur][w4 * 16 + lrow][kk * 16 + lcol]));
            unsigned Bfh[8][2], Bfl[8][2];
#pragma unroll
            for (int nb = 0; nb < 4; nb++) {
                unsigned tmp[4];
                ldsm_x4_t(tmp, s2u(&Bh[cur][kk * 16 + lrow][nb * 16 + lcol]));
                Bfh[nb * 2][0] = tmp[0]; Bfh[nb * 2][1] = tmp[1];
                Bfh[nb * 2 + 1][0] = tmp[2]; Bfh[nb * 2 + 1][1] = tmp[3];
                ldsm_x4_t(tmp, s2u(&Bl[cur][kk * 16 + lrow][nb * 16 + lcol]));
                Bfl[nb * 2][0] = tmp[0]; Bfl[nb * 2][1] = tmp[1];
                Bfl[nb * 2 + 1][0] = tmp[2]; Bfl[nb * 2 + 1][1] = tmp[3];
            }
#pragma unroll
            for (int f = 0; f < 8; f++) {
                mma16816(acc[f], A_h, Bfh[f][0], Bfh[f][1]);
                mma16816(acc[f], A_h, Bfl[f][0], Bfl[f][1]);
                mma16816(acc[f], A_l, Bfh[f][0], Bfh[f][1]);
            }
        }
        if (it + 2 < 16) { issue((it + 2) % 3, it + 2); CP_COMMIT(); }
    }

    __syncthreads();
    if (wg == 1) {
#pragma unroll
        for (int f = 0; f < 8; f++)
#pragma unroll
            for (int h = 0; h < 2; h++)
                *reinterpret_cast<float2*>(&redS[w4][g + h * 8][f * 8 + tg * 2]) =
                    make_float2(acc[f][h * 2], acc[f][h * 2 + 1]);
    }
    __syncthreads();
    if (wg == 0) {
        const int n_lo = n0 + w4 * 16 + g;
#pragma unroll
        for (int f = 0; f < 8; f++) {
            int col = f * 8 + tg * 2;
#pragma unroll
            for (int h = 0; h < 2; h++) {
                float2 r = *reinterpret_cast<const float2*>(&redS[w4][g + h * 8][col]);
                int n = n_lo + h * 8;
                *reinterpret_cast<float2*>(&g_s1[(size_t)n * (BB * DIN) + bd0 + col]) =
                    make_float2(acc[f][h * 2] + r.x, acc[f][h * 2 + 1] + r.y);
            }
        }
    }
}

// ---------------------------------------------------------------------------
// K6: out[b,n,o] = bias[n,o] + sum_{k,i} xg[k][n,b,i] w[n,k,i,o]
// ---------------------------------------------------------------------------
__global__ __launch_bounds__(128) void out_kernel(float* __restrict__ out) {
    const int n = blockIdx.x, t = threadIdx.x;
    __shared__ float wS[KIO];
    __shared__ float xgS[2][BB][DIN];
    __shared__ float bSh[DOUT];
    __shared__ float red[8][BB][68];
    const float* wp = g_w + (size_t)n * KIO;
#pragma unroll
    for (int l = 0; l < 16; l++) {
        int idx4 = t + l * 128;
        *reinterpret_cast<float4*>(&wS[idx4 * 4]) =
            *reinterpret_cast<const float4*>(&wp[idx4 * 4]);
    }
#pragma unroll
    for (int l = 0; l < 2; l++) {
        int idx4 = t + l * 128;
        float* xgFlat = &xgS[0][0][0];
        const float* src = (idx4 < 128) ? (g_sxT + (size_t)n * (BB * DIN) + idx4 * 4)
                                        : (g_s1  + (size_t)n * (BB * DIN) + (idx4 - 128) * 4);
        *reinterpret_cast<float4*>(&xgFlat[idx4 * 4]) =
            *reinterpret_cast<const float4*>(src);
    }
    if (t < DOUT) bSh[t] = g_bias[n * DOUT + t];
    __syncthreads();

    const int sp = t >> 4;
    const int og = t & 15;
    const int o4 = og * 4;
    float acc[BB][4] = {};
#pragma unroll
    for (int ii = 0; ii < 16; ii++) {
        int ki = sp * 16 + ii;
        int k = ki >> 6, i = ki & 63;
        float4 wv = *reinterpret_cast<const float4*>(&wS[ki * 64 + o4]);
#pragma unroll
        for (int b = 0; b < BB; b++) {
            float xv = xgS[k][b][i];
            acc[b][0] += xv * wv.x;
            acc[b][1] += xv * wv.y;
            acc[b][2] += xv * wv.z;
            acc[b][3] += xv * wv.w;
        }
    }
#pragma unroll
    for (int b = 0; b < BB; b++)
        *reinterpret_cast<float4*>(&red[sp][b][o4]) =
            make_float4(acc[b][0], acc[b][1], acc[b][2], acc[b][3]);
    __syncthreads();

    {
        const int b = t >> 4, o4e = (t & 15) * 4;
        float4 r = make_float4(bSh[o4e], bSh[o4e + 1], bSh[o4e + 2], bSh[o4e + 3]);
#pragma unroll
        for (int s = 0; s < 8; s++) {
            float4 p = *reinterpret_cast<const float4*>(&red[s][b][o4e]);
            r.x += p.x; r.y += p.y; r.z += p.z; r.w += p.w;
        }
        *reinterpret_cast<float4*>(&out[((size_t)b * NN + n) * DOUT + o4e]) = r;
    }
}

// ---------------------------------------------------------------------------
extern "C" void kernel_launch(void* const* d_in, const int* in_sizes, int n_in,
                              void* d_out, int out_size) {
    const float* x    = (const float*)d_in[0];   // [8,1024,64]
    const float* E    = (const float*)d_in[1];   // [1024,16]
    const float* pa   = (const float*)d_in[2];   // [8,1024,16]
    const float* Wp   = (const float*)d_in[3];   // [16,2,64,64]
    const float* bp   = (const float*)d_in[4];   // [16,64]
    float* out = (float*)d_out;                  // [8,1024,64]

    sim_kernel<<<NN, 256>>>(E);
    weights_mma_kernel<<<dim3(KIO / 256, NN / 64), 256>>>(E, Wp);
    bias_kernel<<<NN * DOUT / 256, 256>>>(E, bp);
    e_kernel<<<dim3(136, BB), 256>>>(pa);
    sinv_xs_kernel<<<BB * NN / 16, 256>>>(x);
    sx_mma_kernel<<<dim3(NN / 64, BB), 256>>>();
    s1_mma_kernel<<<dim3(NN / 64, BB * DIN / 64), 256>>>();
    out_kernel<<<NN, 128>>>(out);
}

// round 14
// speedup vs baseline: 1.0603x; 1.0603x over previous
#include <cuda_runtime.h>
#include <cuda_bf16.h>
#include <cstdint>

#define NN 1024
#define BB 8
#define DIN 64
#define DOUT 64
#define EMB 16
#define DPE 16
#define KIO 8192   // 2*64*64

// ---- device scratch (no allocations allowed) ----
// e stored CANONICALLY only (upper-tri tiles); lower-tri reads use ldmatrix.trans.
__device__ __nv_bfloat16 g_e_hi[(size_t)BB * NN * NN];   // 16 MB
__device__ __nv_bfloat16 g_e_lo[(size_t)BB * NN * NN];   // 16 MB
__device__ __nv_bfloat16 g_sim_hi[NN * NN];              // 2 MB
__device__ __nv_bfloat16 g_sim_lo[NN * NN];              // 2 MB
__device__ __nv_bfloat16 g_xs_hi[BB * NN * DIN];         // 1 MB  (x*Sinv)
__device__ __nv_bfloat16 g_xs_lo[BB * NN * DIN];         // 1 MB
__device__ __nv_bfloat16 g_sxT_hi[NN * BB * DIN];        // 1 MB
__device__ __nv_bfloat16 g_sxT_lo[NN * BB * DIN];        // 1 MB
__device__ float g_w[NN * KIO];           // 32 MB  weights[n][k][i][o]
__device__ float g_bias[NN * DOUT];       // 256 KB
__device__ float g_part[BB * NN * 16];    // 512 KB row-sum partials
__device__ float g_sxT[NN * BB * DIN];    // 2 MB
__device__ float g_s1[NN * BB * DIN];     // 2 MB

// ---------- helpers ----------
static __device__ __forceinline__ unsigned int s2u(const void* p) {
    return (unsigned int)__cvta_generic_to_shared(p);
}
static __device__ __forceinline__ void ldsm_x4(unsigned r[4], unsigned int addr) {
    asm volatile("ldmatrix.sync.aligned.m8n8.x4.shared.b16 {%0,%1,%2,%3}, [%4];"
        : "=r"(r[0]), "=r"(r[1]), "=r"(r[2]), "=r"(r[3]) : "r"(addr));
}
static __device__ __forceinline__ void ldsm_x4_t(unsigned r[4], unsigned int addr) {
    asm volatile("ldmatrix.sync.aligned.m8n8.x4.trans.shared.b16 {%0,%1,%2,%3}, [%4];"
        : "=r"(r[0]), "=r"(r[1]), "=r"(r[2]), "=r"(r[3]) : "r"(addr));
}
static __device__ __forceinline__ void mma16816(float c[4], const unsigned a[4], const unsigned b0, const unsigned b1) {
    asm volatile("mma.sync.aligned.m16n8k16.row.col.f32.bf16.bf16.f32 "
        "{%0,%1,%2,%3}, {%4,%5,%6,%7}, {%8,%9}, {%0,%1,%2,%3};"
        : "+f"(c[0]), "+f"(c[1]), "+f"(c[2]), "+f"(c[3])
        : "r"(a[0]), "r"(a[1]), "r"(a[2]), "r"(a[3]), "r"(b0), "r"(b1));
}
static __device__ __forceinline__ void cpa16(void* dst, const void* src) {
    unsigned int d = s2u(dst);
    asm volatile("cp.async.ca.shared.global [%0], [%1], 16;" :: "r"(d), "l"(src));
}
#define CP_COMMIT() asm volatile("cp.async.commit_group;" ::: "memory")
#define CP_WAIT1()  asm volatile("cp.async.wait_group 1;" ::: "memory")
#define CP_WAIT0()  asm volatile("cp.async.wait_group 0;" ::: "memory")

static __device__ __forceinline__ void split_store(float v, __nv_bfloat16* hi, __nv_bfloat16* lo, size_t off) {
    __nv_bfloat16 h = __float2bfloat16(v);
    hi[off] = h;
    lo[off] = __float2bfloat16(v - __bfloat162float(h));
}
static __device__ __forceinline__ void split_pair(float v0, float v1,
                                                  __nv_bfloat162& hv, __nv_bfloat162& lv) {
    hv = __floats2bfloat162_rn(v0, v1);
    float2 hf = __bfloat1622float2(hv);
    lv = __floats2bfloat162_rn(v0 - hf.x, v1 - hf.y);
}

// e^{-d} for d >= 0, FFMA-only (no MUFU). Max rel err ~2e-8.
static __device__ __forceinline__ float fexp_neg(float d) {
    float z = d * -1.442695040888963f;       // log2(e)
    z = fmaxf(z, -126.0f);
    float n = rintf(z);
    float f = z - n;
    float p = 1.54035304e-4f;
    p = fmaf(p, f, 1.33335581e-3f);
    p = fmaf(p, f, 9.61812911e-3f);
    p = fmaf(p, f, 5.55041087e-2f);
    p = fmaf(p, f, 2.40226507e-1f);
    p = fmaf(p, f, 6.93147181e-1f);
    p = fmaf(p, f, 1.0f);
    int e = (int)n;
    return p * __int_as_float((127 + e) << 23);
}

// ---------------------------------------------------------------------------
// PREP kernel: fuses three independent preamble kernels (branch on blockIdx.x)
//   [0, 1024)      : sim row i = blockIdx.x        (softmax(relu(E E^T)))
//   [1024, 1536)   : weights mma tile              (E @ Wp, 3-pass bf16 split)
//   [1536, 1792)   : bias chunk                    (E @ bp)
// ---------------------------------------------------------------------------
__global__ __launch_bounds__(256) void prep_kernel(const float* __restrict__ E,
                                                   const float* __restrict__ Wp,
                                                   const float* __restrict__ bp) {
    const int bx = blockIdx.x;
    const int t = threadIdx.x;

    __shared__ float Ei[EMB];
    __shared__ float red[256];
    __shared__ __nv_bfloat16 Ah[64][24], Al[64][24];
    __shared__ __nv_bfloat16 Bh[16][264], Bl[16][264];

    if (bx < 1024) {
        // ---------------- sim ----------------
        const int i = bx;
        if (t < EMB) Ei[t] = E[i * EMB + t];
        __syncthreads();

        float v[4];
        float mx = -1e30f;
#pragma unroll
        for (int r = 0; r < 4; r++) {
            int j = t + r * 256;
            const float4* Ej = reinterpret_cast<const float4*>(E + j * EMB);
            float acc = 0.f;
#pragma unroll
            for (int q = 0; q < 4; q++) {
                float4 e4 = Ej[q];
                acc += Ei[q * 4 + 0] * e4.x + Ei[q * 4 + 1] * e4.y
                     + Ei[q * 4 + 2] * e4.z + Ei[q * 4 + 3] * e4.w;
            }
            acc = fmaxf(acc, 0.f);
            v[r] = acc;
            mx = fmaxf(mx, acc);
        }
        red[t] = mx; __syncthreads();
        for (int s = 128; s > 0; s >>= 1) { if (t < s) red[t] = fmaxf(red[t], red[t + s]); __syncthreads(); }
        mx = red[0]; __syncthreads();

        float sum = 0.f;
#pragma unroll
        for (int r = 0; r < 4; r++) { v[r] = fexp_neg(mx - v[r]); sum += v[r]; }
        red[t] = sum; __syncthreads();
        for (int s = 128; s > 0; s >>= 1) { if (t < s) red[t] += red[t + s]; __syncthreads(); }
        float inv = 1.0f / red[0];
#pragma unroll
        for (int r = 0; r < 4; r++)
            split_store(v[r] * inv, g_sim_hi, g_sim_lo, (size_t)i * NN + t + r * 256);

    } else if (bx < 1536) {
        // ---------------- weights (bf16 mma, 3-pass split) ----------------
        const int q = bx - 1024;               // 0..511
        const int kio0 = (q & 31) * 256;
        const int n0 = (q >> 5) * 64;
        const int warp = t >> 5, lane = t & 31;
        const int g = lane >> 2, tg = lane & 3;
        const int lrow = lane & 15;
        const int lcol = (lane & 16) >> 1;

        {
            int r = t >> 2, q4 = (t & 3) * 4;
            float4 v = *reinterpret_cast<const float4*>(&E[(n0 + r) * EMB + q4]);
            __nv_bfloat162 h0, l0, h1, l1;
            split_pair(v.x, v.y, h0, l0);
            split_pair(v.z, v.w, h1, l1);
            *reinterpret_cast<__nv_bfloat162*>(&Ah[r][q4]) = h0;
            *reinterpret_cast<__nv_bfloat162*>(&Ah[r][q4 + 2]) = h1;
            *reinterpret_cast<__nv_bfloat162*>(&Al[r][q4]) = l0;
            *reinterpret_cast<__nv_bfloat162*>(&Al[r][q4 + 2]) = l1;
        }
#pragma unroll
        for (int l = 0; l < 4; l++) {
            int idx = t + l * 256;
            int r = idx >> 6, c4 = (idx & 63) * 4;
            float4 v = *reinterpret_cast<const float4*>(&Wp[(size_t)r * KIO + kio0 + c4]);
            __nv_bfloat162 h0, l0, h1, l1;
            split_pair(v.x, v.y, h0, l0);
            split_pair(v.z, v.w, h1, l1);
            *reinterpret_cast<__nv_bfloat162*>(&Bh[r][c4]) = h0;
            *reinterpret_cast<__nv_bfloat162*>(&Bh[r][c4 + 2]) = h1;
            *reinterpret_cast<__nv_bfloat162*>(&Bl[r][c4]) = l0;
            *reinterpret_cast<__nv_bfloat162*>(&Bl[r][c4 + 2]) = l1;
        }
        __syncthreads();

        unsigned Bfh[4][2], Bfl[4][2];
#pragma unroll
        for (int nb = 0; nb < 2; nb++) {
            unsigned tmp[4];
            ldsm_x4_t(tmp, s2u(&Bh[lrow][warp * 32 + nb * 16 + lcol]));
            Bfh[nb * 2][0] = tmp[0]; Bfh[nb * 2][1] = tmp[1];
            Bfh[nb * 2 + 1][0] = tmp[2]; Bfh[nb * 2 + 1][1] = tmp[3];
            ldsm_x4_t(tmp, s2u(&Bl[lrow][warp * 32 + nb * 16 + lcol]));
            Bfl[nb * 2][0] = tmp[0]; Bfl[nb * 2][1] = tmp[1];
            Bfl[nb * 2 + 1][0] = tmp[2]; Bfl[nb * 2 + 1][1] = tmp[3];
        }

        float acc[4][4][4] = {};
#pragma unroll
        for (int mf = 0; mf < 4; mf++) {
            unsigned A_h[4], A_l[4];
            ldsm_x4(A_h, s2u(&Ah[mf * 16 + lrow][lcol]));
            ldsm_x4(A_l, s2u(&Al[mf * 16 + lrow][lcol]));
#pragma unroll
            for (int f = 0; f < 4; f++) {
                mma16816(acc[mf][f], A_h, Bfh[f][0], Bfh[f][1]);
                mma16816(acc[mf][f], A_h, Bfl[f][0], Bfl[f][1]);
                mma16816(acc[mf][f], A_l, Bfh[f][0], Bfh[f][1]);
            }
        }

#pragma unroll
        for (int mf = 0; mf < 4; mf++)
#pragma unroll
            for (int f = 0; f < 4; f++)
#pragma unroll
                for (int h = 0; h < 2; h++) {
                    int row = n0 + mf * 16 + g + h * 8;
                    int col = kio0 + warp * 32 + f * 8 + tg * 2;
                    *reinterpret_cast<float2*>(&g_w[(size_t)row * KIO + col]) =
                        make_float2(acc[mf][f][h * 2], acc[mf][f][h * 2 + 1]);
                }

    } else {
        // ---------------- bias ----------------
        int idx = (bx - 1536) * 256 + t;       // 65536
        int n = idx >> 6, o = idx & 63;
        float acc = 0.f;
#pragma unroll
        for (int d = 0; d < EMB; d++) acc += E[n * EMB + d] * bp[d * DOUT + o];
        g_bias[idx] = acc;
    }
}

// ---------------------------------------------------------------------------
// K2: e[b,i,j] = exp(-L1(pa_i, pa_j)) -> bf16 hi/lo, canonical tiles only.
// (R12 form — no reg cap.)
// ---------------------------------------------------------------------------
__global__ __launch_bounds__(256) void e_kernel(const float* __restrict__ pa) {
    const int b = blockIdx.y;
    int rem = blockIdx.x, ti = 0;
    while (rem >= 16 - ti) { rem -= 16 - ti; ti++; }
    const int tjt = ti + rem;
    const int i0 = ti * 64, j0 = tjt * 64;
    const int t = threadIdx.x;
    const int cp = t & 31, rg = t >> 5;
    const int c0 = cp * 2;

    __shared__ float paI[64][20];
    __shared__ float paJ[64][20];
    __shared__ float vS[64][65];
    __shared__ float cpS[8][64];
    __shared__ float rpS[4][64];

    const float* paB = pa + (size_t)b * NN * DPE;
    {
        int r = t >> 2, q4 = (t & 3) * 4;
        *reinterpret_cast<float4*>(&paI[r][q4]) =
            *reinterpret_cast<const float4*>(&paB[(i0 + r) * DPE + q4]);
        *reinterpret_cast<float4*>(&paJ[r][q4]) =
            *reinterpret_cast<const float4*>(&paB[(j0 + r) * DPE + q4]);
    }
    __syncthreads();

    float pj0[16], pj1[16];
#pragma unroll
    for (int q = 0; q < 4; q++) {
        float4 u = *reinterpret_cast<const float4*>(&paJ[c0][q * 4]);
        pj0[q * 4 + 0] = u.x; pj0[q * 4 + 1] = u.y; pj0[q * 4 + 2] = u.z; pj0[q * 4 + 3] = u.w;
        float4 w = *reinterpret_cast<const float4*>(&paJ[c0 + 1][q * 4]);
        pj1[q * 4 + 0] = w.x; pj1[q * 4 + 1] = w.y; pj1[q * 4 + 2] = w.z; pj1[q * 4 + 3] = w.w;
    }

    const unsigned baseD = (unsigned)((b * NN + i0) * NN + j0);
    float cps0 = 0.f, cps1 = 0.f;
#pragma unroll
    for (int s = 0; s < 8; s++) {
        int i = rg * 8 + s;
        float4 p0 = *reinterpret_cast<const float4*>(&paI[i][0]);
        float4 p1 = *reinterpret_cast<const float4*>(&paI[i][4]);
        float4 p2 = *reinterpret_cast<const float4*>(&paI[i][8]);
        float4 p3 = *reinterpret_cast<const float4*>(&paI[i][12]);
        float d0 = (((fabsf(p0.x - pj0[0])  + fabsf(p0.y - pj0[1]))
                  +  (fabsf(p0.z - pj0[2])  + fabsf(p0.w - pj0[3])))
                 +  ((fabsf(p1.x - pj0[4])  + fabsf(p1.y - pj0[5]))
                  +  (fabsf(p1.z - pj0[6])  + fabsf(p1.w - pj0[7]))))
                 + (((fabsf(p2.x - pj0[8])  + fabsf(p2.y - pj0[9]))
                  +  (fabsf(p2.z - pj0[10]) + fabsf(p2.w - pj0[11])))
                 +  ((fabsf(p3.x - pj0[12]) + fabsf(p3.y - pj0[13]))
                  +  (fabsf(p3.z - pj0[14]) + fabsf(p3.w - pj0[15]))));
        float d1 = (((fabsf(p0.x - pj1[0])  + fabsf(p0.y - pj1[1]))
                  +  (fabsf(p0.z - pj1[2])  + fabsf(p0.w - pj1[3])))
                 +  ((fabsf(p1.x - pj1[4])  + fabsf(p1.y - pj1[5]))
                  +  (fabsf(p1.z - pj1[6])  + fabsf(p1.w - pj1[7]))))
                 + (((fabsf(p2.x - pj1[8])  + fabsf(p2.y - pj1[9]))
                  +  (fabsf(p2.z - pj1[10]) + fabsf(p2.w - pj1[11])))
                 +  ((fabsf(p3.x - pj1[12]) + fabsf(p3.y - pj1[13]))
                  +  (fabsf(p3.z - pj1[14]) + fabsf(p3.w - pj1[15]))));
        float v0 = fexp_neg(d0), v1 = fexp_neg(d1);
        vS[i][c0] = v0; vS[i][c0 + 1] = v1;
        cps0 += v0; cps1 += v1;
        __nv_bfloat162 hv, lv; split_pair(v0, v1, hv, lv);
        unsigned off = baseD + (unsigned)i * NN + c0;
        *reinterpret_cast<__nv_bfloat162*>(g_e_hi + off) = hv;
        *reinterpret_cast<__nv_bfloat162*>(g_e_lo + off) = lv;
    }
    cpS[rg][c0] = cps0; cpS[rg][c0 + 1] = cps1;
    __syncthreads();

    {
        int r = t & 63, qq = t >> 6;
        float s = 0.f;
#pragma unroll
        for (int c = 0; c < 16; c++) s += vS[r][qq * 16 + c];
        rpS[qq][r] = s;
    }
    __syncthreads();

    if (t < 64) {
        float rowP = rpS[0][t] + rpS[1][t] + rpS[2][t] + rpS[3][t];
        g_part[((size_t)b * NN + i0 + t) * 16 + tjt] = rowP;
    } else if (t < 128 && ti != tjt) {
        int c = t - 64;
        float colP = 0.f;
#pragma unroll
        for (int q = 0; q < 8; q++) colP += cpS[q][c];
        g_part[((size_t)b * NN + j0 + c) * 16 + ti] = colP;
    }
}

// ---------------------------------------------------------------------------
// K3: merged Sinv + xs:  xs[row,d] = x[row,d] / sum_k part[row][k]
// ---------------------------------------------------------------------------
__global__ __launch_bounds__(256) void sinv_xs_kernel(const float* __restrict__ x) {
    const int row0 = blockIdx.x * 16;
    const int t = threadIdx.x;
    __shared__ float sInv[16];
    if (t < 16) {
        const float* p = g_part + (size_t)(row0 + t) * 16;
        float s = 0.f;
#pragma unroll
        for (int k = 0; k < 16; k++) s += p[k];
        sInv[t] = 1.0f / s;
    }
    __syncthreads();
    const int rloc = t >> 4, d4 = (t & 15) * 4;
    const size_t row = row0 + rloc;
    float4 v = *reinterpret_cast<const float4*>(&x[row * DIN + d4]);
    float s = sInv[rloc];
    v.x *= s; v.y *= s; v.z *= s; v.w *= s;
    __nv_bfloat162 h0, l0, h1, l1;
    split_pair(v.x, v.y, h0, l0);
    split_pair(v.z, v.w, h1, l1);
    *reinterpret_cast<__nv_bfloat162*>(&g_xs_hi[row * DIN + d4]) = h0;
    *reinterpret_cast<__nv_bfloat162*>(&g_xs_hi[row * DIN + d4 + 2]) = h1;
    *reinterpret_cast<__nv_bfloat162*>(&g_xs_lo[row * DIN + d4]) = l0;
    *reinterpret_cast<__nv_bfloat162*>(&g_xs_lo[row * DIN + d4 + 2]) = l1;
}

// ---------------------------------------------------------------------------
// K4: sxT[m][b][d] = sum_c e[b,m,c] * xs[b,c,d]  via bf16 mma (3-pass split)
// Split-K (2 warpgroups, BK=64), 2-stage cp.async (R12 form).
// Lower-tri K-chunks read transposed via ldmatrix.trans.
// grid (16 m-tiles, 8 b)
// ---------------------------------------------------------------------------
__global__ __launch_bounds__(256) void sx_mma_kernel() {
    const int b = blockIdx.y, mt = blockIdx.x, m0 = mt * 64;
    const int t = threadIdx.x;
    const int warp = t >> 5, lane = t & 31;
    const int wg = warp >> 2, w4 = warp & 3;
    const int g = lane >> 2, tg = lane & 3;

    __shared__ __nv_bfloat16 Ah[2][64][72], Al[2][64][72];
    __shared__ __nv_bfloat16 Bh[2][64][72], Bl[2][64][72];
    __shared__ float redS[4][16][64];

    const __nv_bfloat16* eHiB = g_e_hi + (size_t)b * NN * NN;
    const __nv_bfloat16* eLoB = g_e_lo + (size_t)b * NN * NN;
    const __nv_bfloat16* xHi = g_xs_hi + (size_t)b * NN * DIN;
    const __nv_bfloat16* xLo = g_xs_lo + (size_t)b * NN * DIN;

    float acc[8][4] = {};
    const int lrow = lane & 15;
    const int lcol = (lane & 16) >> 1;
    const int trow = ((lane & 16) >> 1) | (lane & 7);   // trans ldsm row
    const int tcol = lane & 8;                          // trans ldsm col

    auto issue = [&](int st, int chunk) {
        int c0 = chunk * 64;
        bool tr = (chunk < mt);
#pragma unroll
        for (int l = 0; l < 2; l++) {
            int idx = t + l * 256;
            int r = idx >> 3, q = (idx & 7) * 8;
            size_t src = tr ? ((size_t)(c0 + r) * NN + m0 + q)
                            : ((size_t)(m0 + r) * NN + c0 + q);
            cpa16(&Ah[st][r][q], eHiB + src);
            cpa16(&Al[st][r][q], eLoB + src);
        }
#pragma unroll
        for (int l = 0; l < 2; l++) {
            int idx = t + l * 256;
            int r = idx >> 3, q = (idx & 7) * 8;
            cpa16(&Bh[st][r][q], &xHi[(size_t)(c0 + r) * DIN + q]);
            cpa16(&Bl[st][r][q], &xLo[(size_t)(c0 + r) * DIN + q]);
        }
    };

    issue(0, 0); CP_COMMIT();
    for (int it = 0; it < 16; it++) {
        int cur = it & 1;
        if (it < 15) { issue(cur ^ 1, it + 1); CP_COMMIT(); CP_WAIT1(); }
        else CP_WAIT0();
        __syncthreads();
        const bool tr = (it < mt);

#pragma unroll
        for (int k16 = 0; k16 < 2; k16++) {
            int kk = wg * 2 + k16;
            unsigned A_h[4], A_l[4];
            if (tr) {
                ldsm_x4_t(A_h, s2u(&Ah[cur][kk * 16 + trow][w4 * 16 + tcol]));
                ldsm_x4_t(A_l, s2u(&Al[cur][kk * 16 + trow][w4 * 16 + tcol]));
            } else {
                ldsm_x4(A_h, s2u(&Ah[cur][w4 * 16 + lrow][kk * 16 + lcol]));
                ldsm_x4(A_l, s2u(&Al[cur][w4 * 16 + lrow][kk * 16 + lcol]));
            }
            unsigned Bfh[8][2], Bfl[8][2];
#pragma unroll
            for (int nb = 0; nb < 4; nb++) {
                unsigned tmp[4];
                ldsm_x4_t(tmp, s2u(&Bh[cur][kk * 16 + lrow][nb * 16 + lcol]));
                Bfh[nb * 2][0] = tmp[0]; Bfh[nb * 2][1] = tmp[1];
                Bfh[nb * 2 + 1][0] = tmp[2]; Bfh[nb * 2 + 1][1] = tmp[3];
                ldsm_x4_t(tmp, s2u(&Bl[cur][kk * 16 + lrow][nb * 16 + lcol]));
                Bfl[nb * 2][0] = tmp[0]; Bfl[nb * 2][1] = tmp[1];
                Bfl[nb * 2 + 1][0] = tmp[2]; Bfl[nb * 2 + 1][1] = tmp[3];
            }
#pragma unroll
            for (int f = 0; f < 8; f++) {
                mma16816(acc[f], A_h, Bfh[f][0], Bfh[f][1]);
                mma16816(acc[f], A_h, Bfl[f][0], Bfl[f][1]);
                mma16816(acc[f], A_l, Bfh[f][0], Bfh[f][1]);
            }
        }
        __syncthreads();
    }

    if (wg == 1) {
#pragma unroll
        for (int f = 0; f < 8; f++)
#pragma unroll
            for (int h = 0; h < 2; h++)
                *reinterpret_cast<float2*>(&redS[w4][g + h * 8][f * 8 + tg * 2]) =
                    make_float2(acc[f][h * 2], acc[f][h * 2 + 1]);
    }
    __syncthreads();
    if (wg == 0) {
        const int m_lo = m0 + w4 * 16 + g;
#pragma unroll
        for (int f = 0; f < 8; f++) {
            int col = f * 8 + tg * 2;
#pragma unroll
            for (int h = 0; h < 2; h++) {
                float2 r = *reinterpret_cast<const float2*>(&redS[w4][g + h * 8][col]);
                float vx = acc[f][h * 2] + r.x, vy = acc[f][h * 2 + 1] + r.y;
                int m = m_lo + h * 8;
                size_t o = ((size_t)m * BB + b) * DIN + col;
                *reinterpret_cast<float2*>(&g_sxT[o]) = make_float2(vx, vy);
                __nv_bfloat162 hv, lv; split_pair(vx, vy, hv, lv);
                *reinterpret_cast<__nv_bfloat162*>(&g_sxT_hi[o]) = hv;
                *reinterpret_cast<__nv_bfloat162*>(&g_sxT_lo[o]) = lv;
            }
        }
    }
}

// ---------------------------------------------------------------------------
// K5: s1[n][bd] = sum_m sim[n,m] * sxT[m][bd]  — split-K, 2-stage (R12 form).
// grid (16 n-tiles, 8 bd-tiles)
// ---------------------------------------------------------------------------
__global__ __launch_bounds__(256) void s1_mma_kernel() {
    const int n0 = blockIdx.x * 64, bd0 = blockIdx.y * 64;
    const int t = threadIdx.x;
    const int warp = t >> 5, lane = t & 31;
    const int wg = warp >> 2, w4 = warp & 3;
    const int g = lane >> 2, tg = lane & 3;

    __shared__ __nv_bfloat16 Ah[2][64][72], Al[2][64][72];
    __shared__ __nv_bfloat16 Bh[2][64][72], Bl[2][64][72];
    __shared__ float redS[4][16][64];

    const __nv_bfloat16* aHi = g_sim_hi + (size_t)n0 * NN;
    const __nv_bfloat16* aLo = g_sim_lo + (size_t)n0 * NN;

    float acc[8][4] = {};
    const int lrow = lane & 15;
    const int lcol = (lane & 16) >> 1;

    auto issue = [&](int st, int chunk) {
        int c0 = chunk * 64;
#pragma unroll
        for (int l = 0; l < 2; l++) {
            int idx = t + l * 256;
            int r = idx >> 3, q = (idx & 7) * 8;
            cpa16(&Ah[st][r][q], &aHi[(size_t)r * NN + c0 + q]);
            cpa16(&Al[st][r][q], &aLo[(size_t)r * NN + c0 + q]);
        }
#pragma unroll
        for (int l = 0; l < 2; l++) {
            int idx = t + l * 256;
            int r = idx >> 3, q = (idx & 7) * 8;
            cpa16(&Bh[st][r][q], &g_sxT_hi[(size_t)(c0 + r) * (BB * DIN) + bd0 + q]);
            cpa16(&Bl[st][r][q], &g_sxT_lo[(size_t)(c0 + r) * (BB * DIN) + bd0 + q]);
        }
    };

    issue(0, 0); CP_COMMIT();
    for (int it = 0; it < 16; it++) {
        int cur = it & 1;
        if (it < 15) { issue(cur ^ 1, it + 1); CP_COMMIT(); CP_WAIT1(); }
        else CP_WAIT0();
        __syncthreads();

#pragma unroll
        for (int k16 = 0; k16 < 2; k16++) {
            int kk = wg * 2 + k16;
            unsigned A_h[4], A_l[4];
            ldsm_x4(A_h, s2u(&Ah[cur][w4 * 16 + lrow][kk * 16 + lcol]));
            ldsm_x4(A_l, s2u(&Al[cur][w4 * 16 + lrow][kk * 16 + lcol]));
            unsigned Bfh[8][2], Bfl[8][2];
#pragma unroll
            for (int nb = 0; nb < 4; nb++) {
                unsigned tmp[4];
                ldsm_x4_t(tmp, s2u(&Bh[cur][kk * 16 + lrow][nb * 16 + lcol]));
                Bfh[nb * 2][0] = tmp[0]; Bfh[nb * 2][1] = tmp[1];
                Bfh[nb * 2 + 1][0] = tmp[2]; Bfh[nb * 2 + 1][1] = tmp[3];
                ldsm_x4_t(tmp, s2u(&Bl[cur][kk * 16 + lrow][nb * 16 + lcol]));
                Bfl[nb * 2][0] = tmp[0]; Bfl[nb * 2][1] = tmp[1];
                Bfl[nb * 2 + 1][0] = tmp[2]; Bfl[nb * 2 + 1][1] = tmp[3];
            }
#pragma unroll
            for (int f = 0; f < 8; f++) {
                mma16816(acc[f], A_h, Bfh[f][0], Bfh[f][1]);
                mma16816(acc[f], A_h, Bfl[f][0], Bfl[f][1]);
                mma16816(acc[f], A_l, Bfh[f][0], Bfh[f][1]);
            }
        }
        __syncthreads();
    }

    if (wg == 1) {
#pragma unroll
        for (int f = 0; f < 8; f++)
#pragma unroll
            for (int h = 0; h < 2; h++)
                *reinterpret_cast<float2*>(&redS[w4][g + h * 8][f * 8 + tg * 2]) =
                    make_float2(acc[f][h * 2], acc[f][h * 2 + 1]);
    }
    __syncthreads();
    if (wg == 0) {
        const int n_lo = n0 + w4 * 16 + g;
#pragma unroll
        for (int f = 0; f < 8; f++) {
            int col = f * 8 + tg * 2;
#pragma unroll
            for (int h = 0; h < 2; h++) {
                float2 r = *reinterpret_cast<const float2*>(&redS[w4][g + h * 8][col]);
                int n = n_lo + h * 8;
                *reinterpret_cast<float2*>(&g_s1[(size_t)n * (BB * DIN) + bd0 + col]) =
                    make_float2(acc[f][h * 2] + r.x, acc[f][h * 2 + 1] + r.y);
            }
        }
    }
}

// ---------------------------------------------------------------------------
// K6: out[b,n,o] = bias[n,o] + sum_{k,i} xg[k][n,b,i] w[n,k,i,o]
// ---------------------------------------------------------------------------
__global__ __launch_bounds__(128) void out_kernel(float* __restrict__ out) {
    const int n = blockIdx.x, t = threadIdx.x;
    __shared__ float wS[KIO];
    __shared__ float xgS[2][BB][DIN];
    __shared__ float bSh[DOUT];
    __shared__ float red[8][BB][68];
    const float* wp = g_w + (size_t)n * KIO;
#pragma unroll
    for (int l = 0; l < 16; l++) {
        int idx4 = t + l * 128;
        *reinterpret_cast<float4*>(&wS[idx4 * 4]) =
            *reinterpret_cast<const float4*>(&wp[idx4 * 4]);
    }
#pragma unroll
    for (int l = 0; l < 2; l++) {
        int idx4 = t + l * 128;
        float* xgFlat = &xgS[0][0][0];
        const float* src = (idx4 < 128) ? (g_sxT + (size_t)n * (BB * DIN) + idx4 * 4)
                                        : (g_s1  + (size_t)n * (BB * DIN) + (idx4 - 128) * 4);
        *reinterpret_cast<float4*>(&xgFlat[idx4 * 4]) =
            *reinterpret_cast<const float4*>(src);
    }
    if (t < DOUT) bSh[t] = g_bias[n * DOUT + t];
    __syncthreads();

    const int sp = t >> 4;
    const int og = t & 15;
    const int o4 = og * 4;
    float acc[BB][4] = {};
#pragma unroll
    for (int ii = 0; ii < 16; ii++) {
        int ki = sp * 16 + ii;
        int k = ki >> 6, i = ki & 63;
        float4 wv = *reinterpret_cast<const float4*>(&wS[ki * 64 + o4]);
#pragma unroll
        for (int b = 0; b < BB; b++) {
            float xv = xgS[k][b][i];
            acc[b][0] += xv * wv.x;
            acc[b][1] += xv * wv.y;
            acc[b][2] += xv * wv.z;
            acc[b][3] += xv * wv.w;
        }
    }
#pragma unroll
    for (int b = 0; b < BB; b++)
        *reinterpret_cast<float4*>(&red[sp][b][o4]) =
            make_float4(acc[b][0], acc[b][1], acc[b][2], acc[b][3]);
    __syncthreads();

    {
        const int b = t >> 4, o4e = (t & 15) * 4;
        float4 r = make_float4(bSh[o4e], bSh[o4e + 1], bSh[o4e + 2], bSh[o4e + 3]);
#pragma unroll
        for (int s = 0; s < 8; s++) {
            float4 p = *reinterpret_cast<const float4*>(&red[s][b][o4e]);
            r.x += p.x; r.y += p.y; r.z += p.z; r.w += p.w;
        }
        *reinterpret_cast<float4*>(&out[((size_t)b * NN + n) * DOUT + o4e]) = r;
    }
}

// ---------------------------------------------------------------------------
extern "C" void kernel_launch(void* const* d_in, const int* in_sizes, int n_in,
                              void* d_out, int out_size) {
    const float* x    = (const float*)d_in[0];   // [8,1024,64]
    const float* E    = (const float*)d_in[1];   // [1024,16]
    const float* pa   = (const float*)d_in[2];   // [8,1024,16]
    const float* Wp   = (const float*)d_in[3];   // [16,2,64,64]
    const float* bp   = (const float*)d_in[4];   // [16,64]
    float* out = (float*)d_out;                  // [8,1024,64]

    prep_kernel<<<1792, 256>>>(E, Wp, bp);       // sim + weights + bias fused
    e_kernel<<<dim3(136, BB), 256>>>(pa);
    sinv_xs_kernel<<<BB * NN / 16, 256>>>(x);
    sx_mma_kernel<<<dim3(NN / 64, BB), 256>>>();
    s1_mma_kernel<<<dim3(NN / 64, BB * DIN / 64), 256>>>();
    out_kernel<<<NN, 128>>>(out);
}